// round 7
// baseline (speedup 1.0000x reference)
#include <cuda_runtime.h>
#include <math.h>

#define NB 16
#define NC 64
#define NH 128
#define NW 128
#define PI2 6.283185307179586f

// ---------------- scratch ------------------------------------------------
__device__ float2 d_X [NB*256*64];        // [b][kl][i]
__device__ float2 d_Y [NB*256*64];        // [b][kl][o]
__device__ float2 d_Z1[NB*NH*64*16];      // [b][h][o][l]  (tf32-rounded)
__device__ float2 d_Wt[256*64*64];        // [kl][i*64+o]
__device__ float  d_proj[NB*NC];
__device__ float  d_Eout[32*128];         // rows 0..15: cos(2pi l w/128); 16..31: -sin
__device__ float2 d_twdp[128];            // e^{+i 2pi m/128}
__device__ float2 d_twdm[128];            // e^{-i 2pi m/128}

// ---------------- helpers ------------------------------------------------
__device__ __forceinline__ unsigned tf32u(float f) {
    unsigned r; asm("cvt.rna.tf32.f32 %0, %1;" : "=r"(r) : "f"(f)); return r;
}
__device__ __forceinline__ float tf32f(float f) { return __uint_as_float(tf32u(f)); }
__device__ __forceinline__ void mma_tf32(float* c,
    unsigned a0, unsigned a1, unsigned a2, unsigned a3, unsigned b0, unsigned b1) {
    asm volatile(
        "mma.sync.aligned.m16n8k8.row.col.f32.tf32.tf32.f32 "
        "{%0,%1,%2,%3}, {%4,%5,%6,%7}, {%8,%9}, {%0,%1,%2,%3};"
        : "+f"(c[0]), "+f"(c[1]), "+f"(c[2]), "+f"(c[3])
        : "r"(a0), "r"(a1), "r"(a2), "r"(a3), "r"(b0), "r"(b1));
}
__device__ __forceinline__ unsigned s2u(const void* p) {
    unsigned a;
    asm("{ .reg .u64 t; cvta.to.shared.u64 t, %1; cvt.u32.u64 %0, t; }" : "=r"(a) : "l"(p));
    return a;
}
__device__ __forceinline__ void ldsm4(unsigned &r0, unsigned &r1, unsigned &r2,
                                      unsigned &r3, unsigned a) {
    asm volatile("ldmatrix.sync.aligned.m8n8.x4.shared.b16 {%0,%1,%2,%3}, [%4];"
        : "=r"(r0), "=r"(r1), "=r"(r2), "=r"(r3) : "r"(a));
}

// ---------------- precompute twiddles ------------------------------------
__global__ void k_prep() {
    int t = threadIdx.x;                       // 256
    for (int idx = t; idx < 4096; idx += 256) {
        int r = idx >> 7, w = idx & 127;
        int l = r & 15;
        float s, c;
        sincosf(PI2 * (float)((l*w) & 127) * (1.f/128.f), &s, &c);
        d_Eout[idx] = tf32f(r < 16 ? c : -s);
    }
    if (t < 128) {
        float s, c; sincosf(PI2 * t * (1.f/128.f), &s, &c);
        d_twdp[t] = make_float2(c, s);
        d_twdm[t] = make_float2(c, -s);
    }
}

// ---------------- temb projection ---------------------------------------
__global__ void k_proj(const float* __restrict__ temb,
                       const float* __restrict__ twm,
                       const float* __restrict__ tbv) {
    __shared__ float s_silu[512];
    int b = blockIdx.x, cg = blockIdx.y, t = threadIdx.x;   // 256 threads
    for (int j = t; j < 512; j += 256) {
        float v = temb[b*512 + j];
        s_silu[j] = v / (1.f + __expf(-v));
    }
    __syncthreads();
    int w = t >> 5, lane = t & 31;
    int c = cg*8 + w;
    float acc = 0.f;
    #pragma unroll 4
    for (int j = lane; j < 512; j += 32) acc += s_silu[j] * twm[c*512 + j];
    #pragma unroll
    for (int off = 16; off > 0; off >>= 1)
        acc += __shfl_xor_sync(0xffffffffu, acc, off);
    if (lane == 0) d_proj[b*64 + c] = acc + tbv[c];
}

// ---------------- weight transpose: [i,o,k,l] -> [kl][i*64+o] ------------
__global__ void k_wt(const float* __restrict__ wr, const float* __restrict__ wi) {
    __shared__ float tr[32][33], ti[32][33];
    int kl0 = blockIdx.x * 32, io0 = blockIdx.y * 32;
    for (int r = threadIdx.y; r < 32; r += 8) {
        tr[r][threadIdx.x] = wr[(io0 + r)*256 + kl0 + threadIdx.x];
        ti[r][threadIdx.x] = wi[(io0 + r)*256 + kl0 + threadIdx.x];
    }
    __syncthreads();
    for (int r = threadIdx.y; r < 32; r += 8) {
        d_Wt[(kl0 + r)*4096 + io0 + threadIdx.x] =
            make_float2(tr[threadIdx.x][r], ti[threadIdx.x][r]);
    }
}

// ---------------- forward truncated DFT ----------------------------------
#define XP 132
#define ESP 132
#define FWD_SMEM (128*XP*4 + 32*ESP*4 + 32*129*4 + 128*8)
__global__ __launch_bounds__(256) void k_fwd(const float* __restrict__ x) {
    extern __shared__ float sm[];
    float*  xs  = sm;                          // [128 h][XP]
    float*  Es  = xs + 128*XP;                 // [32 n][ESP]  (n<16:cos_l, n>=16:-sin_l)
    float*  A1  = Es + 32*ESP;                 // [32 n][129 h]
    float2* twd = (float2*)(A1 + 32*129);      // e^{-i 2pi m/128}

    int t  = threadIdx.x;                      // 256 = 8 warps
    int bi = blockIdx.x, b = bi >> 6, ci = bi & 63;

    const float4* xg = (const float4*)(x + (size_t)bi * 16384);
    for (int idx = t; idx < 4096; idx += 256) {
        int hh = idx >> 5, w4 = idx & 31;
        float4 v = xg[hh*32 + w4];
        int base = hh*XP + w4*4;
        xs[base+0] = tf32f(v.x); xs[base+1] = tf32f(v.y);
        xs[base+2] = tf32f(v.z); xs[base+3] = tf32f(v.w);
    }
    for (int idx = t; idx < 4096; idx += 256)
        Es[(idx >> 7)*ESP + (idx & 127)] = d_Eout[idx];
    if (t < 128) twd[t] = d_twdm[t];
    __syncthreads();

    int lane = t & 31, warp = t >> 5;
    int qr = lane >> 2, qc = lane & 3;
    int lr = lane & 7, lg = lane >> 3;

    // GEMM1: M=128 (h), N=32 (n), K=128 (w)
    {
        int m0 = warp * 16;
        unsigned aBase = s2u(xs) + ((m0 + lr + (lg & 1)*8)*XP + (lg >> 1)*4)*4;
        unsigned bBase = s2u(Es) + ((lr + (lg >> 1)*8)*ESP + (lg & 1)*4)*4;
        float acc[4][4];
        #pragma unroll
        for (int a = 0; a < 4; a++)
            #pragma unroll
            for (int j = 0; j < 4; j++) acc[a][j] = 0.f;
        #pragma unroll
        for (int kk = 0; kk < 16; kk++) {
            unsigned a0, a1, a2, a3;
            ldsm4(a0, a1, a2, a3, aBase + kk*32);
            #pragma unroll
            for (int p = 0; p < 2; p++) {
                unsigned b0, b1, b2, b3;
                ldsm4(b0, b1, b2, b3, bBase + p*16*ESP*4 + kk*32);
                mma_tf32(acc[2*p],   a0, a1, a2, a3, b0, b1);
                mma_tf32(acc[2*p+1], a0, a1, a2, a3, b2, b3);
            }
        }
        #pragma unroll
        for (int nt = 0; nt < 4; nt++) {
            int n0c = nt*8 + qc*2;
            A1[ n0c   *129 + m0 + qr    ] = acc[nt][0];
            A1[(n0c+1)*129 + m0 + qr    ] = acc[nt][1];
            A1[ n0c   *129 + m0 + qr + 8] = acc[nt][2];
            A1[(n0c+1)*129 + m0 + qr + 8] = acc[nt][3];
        }
    }
    __syncthreads();

    // Stage 2: X[k,l] = (1/128) sum_h (Gr + i Gi) e^{-i 2pi k h/128}
    {
        int k = t >> 4, l = t & 15;
        float xr = 0.f, xi = 0.f;
        for (int h2 = 0; h2 < 128; h2++) {
            float ar = A1[l*129 + h2], ai = A1[(16+l)*129 + h2];
            float2 e = twd[(k*h2) & 127];
            xr += ar*e.x - ai*e.y;
            xi += ar*e.y + ai*e.x;
        }
        d_X[((size_t)b*256 + t)*64 + ci] = make_float2(xr*(1.f/128.f), xi*(1.f/128.f));
    }
}

// ---------------- per-mode channel mixing (o-split x4) -------------------
__global__ __launch_bounds__(256) void k_mix() {
    __shared__ float2 Ws[64*16];    // [i][ol]
    __shared__ float2 Xs[16*64];    // [b][i]
    int kl = blockIdx.x, oq = blockIdx.y, t = threadIdx.x;
    for (int idx = t; idx < 1024; idx += 256)
        Ws[idx] = d_Wt[kl*4096 + (idx >> 4)*64 + oq*16 + (idx & 15)];
    for (int idx = t; idx < 1024; idx += 256)
        Xs[idx] = d_X[((size_t)(idx >> 6)*256 + kl)*64 + (idx & 63)];
    __syncthreads();
    int ol = t & 15, b = t >> 4;
    float yr = 0.f, yi = 0.f;
    #pragma unroll 8
    for (int i = 0; i < 64; i++) {
        float2 xv = Xs[b*64 + i];
        float2 wv = Ws[i*16 + ol];
        yr += xv.x*wv.x - xv.y*wv.y;
        yi += xv.x*wv.y + xv.y*wv.x;
    }
    d_Y[((size_t)b*256 + kl)*64 + oq*16 + ol] = make_float2(yr, yi);
}

// ---------------- inverse stage 1 (over k) -------------------------------
__global__ __launch_bounds__(256) void k_invh() {
    __shared__ float2 Ys[256];
    __shared__ float2 twd[128];
    int t = threadIdx.x, bo = blockIdx.x;
    int b = bo >> 6, o = bo & 63;
    if (t < 128) twd[t] = d_twdp[t];
    Ys[t] = d_Y[((size_t)b*256 + t)*64 + o];
    __syncthreads();
    #pragma unroll
    for (int rep = 0; rep < 8; rep++) {
        int idx = rep*256 + t;
        int h = idx >> 4, l = idx & 15;
        float zr = 0.f, zi = 0.f;
        #pragma unroll
        for (int k = 0; k < 16; k++) {
            float2 y = Ys[k*16 + l];
            float2 e = twd[(k*h) & 127];
            zr += y.x*e.x - y.y*e.y;
            zi += y.x*e.y + y.y*e.x;
        }
        float f = (l == 0 ? 1.f : 2.f) * (1.f/128.f);
        d_Z1[(((size_t)b*128 + h)*64 + o)*16 + l] =
            make_float2(tf32f(zr*f), tf32f(zi*f));
    }
}

// ---------------- fused final: C[64o,128w] = A[64,96] @ B[96,128] --------
#define KP 100   // Bt pitch ([n][k] layout, 16B-aligned rows)
#define AP 100
#define OUT_SMEM (128*KP*4 + 64*AP*4 + 128*4)
__global__ __launch_bounds__(256) void k_out(const float* __restrict__ x,
                                             const float* __restrict__ bw,
                                             const float* __restrict__ bb,
                                             float* __restrict__ out) {
    extern __shared__ float sm[];
    float* Bt  = sm;               // [128 w][KP]  (transposed B)
    float* As  = Bt + 128*KP;      // [64 o][AP]
    float* bbp = As + 64*AP;

    int t = threadIdx.x;           // 256 = 8 warps
    int b = blockIdx.x >> 7, h = blockIdx.x & 127;

    // Bt cols 0..63: x[b,i,h,:] transposed -> [w][i]
    const float4* xg = (const float4*)x;
    for (int idx = t; idx < 2048; idx += 256) {
        int i = idx >> 5, w4 = idx & 31;
        float4 v = xg[(((size_t)(b*64 + i))*128 + h)*32 + w4];
        Bt[(w4*4+0)*KP + i] = tf32f(v.x);
        Bt[(w4*4+1)*KP + i] = tf32f(v.y);
        Bt[(w4*4+2)*KP + i] = tf32f(v.z);
        Bt[(w4*4+3)*KP + i] = tf32f(v.w);
    }
    // Bt cols 64..95: twiddles (precomputed tf32)
    for (int idx = t; idx < 4096; idx += 256) {
        int lc = idx >> 7, w = idx & 127;
        Bt[w*KP + 64 + lc] = d_Eout[idx];
    }
    // As cols 0..63: bw[o][i];  cols 64..95: Zr|Zi
    for (int idx = t; idx < 4096; idx += 256)
        As[(idx >> 6)*AP + (idx & 63)] = tf32f(bw[idx]);
    for (int idx = t; idx < 1024; idx += 256) {
        int o = idx >> 4, l = idx & 15;
        float2 z = d_Z1[(((size_t)b*128 + h)*64 + o)*16 + l];
        As[o*AP + 64 + l] = z.x;
        As[o*AP + 80 + l] = z.y;
    }
    if (t < 64) bbp[t] = bb[t];
    else if (t < 128) bbp[t] = d_proj[b*64 + (t - 64)];
    __syncthreads();

    int lane = t & 31, warp = t >> 5;
    int m0 = (warp & 3) * 16, n0 = (warp >> 2) * 64;
    int qr = lane >> 2, qc = lane & 3;
    int lr = lane & 7, lg = lane >> 3;

    unsigned aBase = s2u(As) + ((m0 + lr + (lg & 1)*8)*AP + (lg >> 1)*4)*4;
    unsigned bBase = s2u(Bt) + ((n0 + lr + (lg >> 1)*8)*KP + (lg & 1)*4)*4;

    float acc[8][4];
    #pragma unroll
    for (int nt = 0; nt < 8; nt++)
        #pragma unroll
        for (int j = 0; j < 4; j++) acc[nt][j] = 0.f;

    #pragma unroll
    for (int kk = 0; kk < 12; kk++) {
        unsigned a0, a1, a2, a3;
        ldsm4(a0, a1, a2, a3, aBase + kk*32);
        #pragma unroll
        for (int p = 0; p < 4; p++) {
            unsigned b0, b1, b2, b3;
            ldsm4(b0, b1, b2, b3, bBase + p*16*KP*4 + kk*32);
            mma_tf32(acc[2*p],   a0, a1, a2, a3, b0, b1);
            mma_tf32(acc[2*p+1], a0, a1, a2, a3, b2, b3);
        }
    }

    #pragma unroll
    for (int nt = 0; nt < 8; nt++) {
        #pragma unroll
        for (int half = 0; half < 2; half++) {
            int o = m0 + qr + half*8;
            float bias = bbp[o], pr = bbp[64 + o];
            float v0 = acc[nt][half*2 + 0] + bias;
            float v1 = acc[nt][half*2 + 1] + bias;
            v0 = 0.5f * v0 * (1.f + erff(v0 * 0.70710678118f)) + pr;
            v1 = 0.5f * v1 * (1.f + erff(v1 * 0.70710678118f)) + pr;
            int w = n0 + nt*8 + qc*2;
            *(float2*)(out + (((size_t)(b*64 + o))*128 + h)*128 + w) =
                make_float2(v0, v1);
        }
    }
}

// ---------------- launcher ----------------------------------------------
extern "C" void kernel_launch(void* const* d_in, const int* in_sizes, int n_in,
                              void* d_out, int out_size) {
    const float* x    = (const float*)d_in[0];
    const float* temb = (const float*)d_in[1];
    const float* wr   = (const float*)d_in[2];
    const float* wi   = (const float*)d_in[3];
    const float* bw   = (const float*)d_in[4];
    const float* bb   = (const float*)d_in[5];
    const float* twm  = (const float*)d_in[6];
    const float* tbv  = (const float*)d_in[7];
    float* out = (float*)d_out;

    cudaFuncSetAttribute(k_fwd, cudaFuncAttributeMaxDynamicSharedMemorySize, FWD_SMEM);
    cudaFuncSetAttribute(k_out, cudaFuncAttributeMaxDynamicSharedMemorySize, OUT_SMEM);

    k_prep<<<1, 256>>>();
    k_proj<<<dim3(NB, 8), 256>>>(temb, twm, tbv);
    k_wt  <<<dim3(8, 128), dim3(32, 8)>>>(wr, wi);
    k_fwd <<<NB*NC, 256, FWD_SMEM>>>(x);
    k_mix <<<dim3(256, 4), 256>>>();
    k_invh<<<NB*NC, 256>>>();
    k_out <<<NB*NH, 256, OUT_SMEM>>>(x, bw, bb, out);
}

// round 8
// speedup vs baseline: 1.5682x; 1.5682x over previous
#include <cuda_runtime.h>
#include <math.h>

#define NB 16
#define NC 64
#define NH 128
#define NW 128
#define PI2 6.283185307179586f

// ---------------- scratch ------------------------------------------------
__device__ float  d_P [1024*4096];        // [bi][n(0..31: Pr|Pi rows)][h]
__device__ float2 d_X [NB*256*64];        // [b][kl][i]
__device__ float2 d_Y [NB*256*64];        // [b][kl][o]
__device__ float2 d_Z1[NB*NH*64*16];      // [b][h][o][l]  (tf32-rounded)
__device__ float2 d_Wt[256*64*64];        // [kl][i*64+o]
__device__ float  d_proj[NB*NC];
__device__ float  d_Eout[32*128];         // rows 0..15: cos(2pi l w/128); 16..31: -sin
__device__ float2 d_twdp[128];            // e^{+i 2pi m/128}

// ---------------- helpers ------------------------------------------------
__device__ __forceinline__ unsigned tf32u(float f) {
    unsigned r; asm("cvt.rna.tf32.f32 %0, %1;" : "=r"(r) : "f"(f)); return r;
}
__device__ __forceinline__ float tf32f(float f) { return __uint_as_float(tf32u(f)); }
__device__ __forceinline__ void mma_tf32(float* c,
    unsigned a0, unsigned a1, unsigned a2, unsigned a3, unsigned b0, unsigned b1) {
    asm volatile(
        "mma.sync.aligned.m16n8k8.row.col.f32.tf32.tf32.f32 "
        "{%0,%1,%2,%3}, {%4,%5,%6,%7}, {%8,%9}, {%0,%1,%2,%3};"
        : "+f"(c[0]), "+f"(c[1]), "+f"(c[2]), "+f"(c[3])
        : "r"(a0), "r"(a1), "r"(a2), "r"(a3), "r"(b0), "r"(b1));
}
__device__ __forceinline__ unsigned s2u(const void* p) {
    unsigned a;
    asm("{ .reg .u64 t; cvta.to.shared.u64 t, %1; cvt.u32.u64 %0, t; }" : "=r"(a) : "l"(p));
    return a;
}
__device__ __forceinline__ void ldsm4(unsigned &r0, unsigned &r1, unsigned &r2,
                                      unsigned &r3, unsigned a) {
    asm volatile("ldmatrix.sync.aligned.m8n8.x4.shared.b16 {%0,%1,%2,%3}, [%4];"
        : "=r"(r0), "=r"(r1), "=r"(r2), "=r"(r3) : "r"(a));
}

// ---------------- precompute ---------------------------------------------
__global__ void k_prep() {
    int t = threadIdx.x;                       // 256
    for (int idx = t; idx < 4096; idx += 256) {
        int r = idx >> 7, w = idx & 127;
        int l = r & 15;
        float s, c;
        sincosf(PI2 * (float)((l*w) & 127) * (1.f/128.f), &s, &c);
        d_Eout[idx] = tf32f(r < 16 ? c : -s);
    }
    if (t < 128) {
        float s, c; sincosf(PI2 * t * (1.f/128.f), &s, &c);
        d_twdp[t] = make_float2(c, s);
    }
}

// ---------------- temb projection ---------------------------------------
__global__ void k_proj(const float* __restrict__ temb,
                       const float* __restrict__ twm,
                       const float* __restrict__ tbv) {
    __shared__ float s_silu[512];
    int b = blockIdx.x, cg = blockIdx.y, t = threadIdx.x;   // 256 threads
    for (int j = t; j < 512; j += 256) {
        float v = temb[b*512 + j];
        s_silu[j] = v / (1.f + __expf(-v));
    }
    __syncthreads();
    int w = t >> 5, lane = t & 31;
    int c = cg*8 + w;
    float acc = 0.f;
    #pragma unroll 4
    for (int j = lane; j < 512; j += 32) acc += s_silu[j] * twm[c*512 + j];
    #pragma unroll
    for (int off = 16; off > 0; off >>= 1)
        acc += __shfl_xor_sync(0xffffffffu, acc, off);
    if (lane == 0) d_proj[b*64 + c] = acc + tbv[c];
}

// ---------------- weight transpose: [i,o,k,l] -> [kl][i*64+o] ------------
__global__ void k_wt(const float* __restrict__ wr, const float* __restrict__ wi) {
    __shared__ float tr[32][33], ti[32][33];
    int kl0 = blockIdx.x * 32, io0 = blockIdx.y * 32;
    for (int r = threadIdx.y; r < 32; r += 8) {
        tr[r][threadIdx.x] = wr[(io0 + r)*256 + kl0 + threadIdx.x];
        ti[r][threadIdx.x] = wi[(io0 + r)*256 + kl0 + threadIdx.x];
    }
    __syncthreads();
    for (int r = threadIdx.y; r < 32; r += 8) {
        d_Wt[(kl0 + r)*4096 + io0 + threadIdx.x] =
            make_float2(tr[threadIdx.x][r], ti[threadIdx.x][r]);
    }
}

// ---------------- fwd stage A: P[bi][n][h] = x(h-tile) @ E^T --------------
// C[h(32), n(32)] = sum_w x[h,w] * Eout[n,w];  grid (1024 bi, 4 hq), 128 thr
__global__ __launch_bounds__(128) void k_fwdA(const float* __restrict__ x) {
    __shared__ float xs[32*132];
    __shared__ float Es[32*132];
    int t = threadIdx.x;
    int bi = blockIdx.x, hq = blockIdx.y;

    const float4* xg = (const float4*)(x + (size_t)bi*16384 + hq*32*128);
    for (int idx = t; idx < 1024; idx += 128) {
        int hh = idx >> 5, w4 = idx & 31;
        float4 v = xg[hh*32 + w4];
        int base = hh*132 + w4*4;
        xs[base+0] = tf32f(v.x); xs[base+1] = tf32f(v.y);
        xs[base+2] = tf32f(v.z); xs[base+3] = tf32f(v.w);
    }
    for (int idx = t; idx < 4096; idx += 128)
        Es[(idx >> 7)*132 + (idx & 127)] = d_Eout[idx];
    __syncthreads();

    int lane = t & 31, warp = t >> 5;
    int m0 = (warp & 1)*16, n0 = (warp >> 1)*16;
    int qr = lane >> 2, qc = lane & 3, lr = lane & 7, lg = lane >> 3;

    unsigned aBase = s2u(xs) + ((m0 + lr + (lg & 1)*8)*132 + (lg >> 1)*4)*4;
    unsigned bBase = s2u(Es) + ((n0 + lr + (lg >> 1)*8)*132 + (lg & 1)*4)*4;

    float acc[2][4];
    #pragma unroll
    for (int u = 0; u < 2; u++)
        #pragma unroll
        for (int j = 0; j < 4; j++) acc[u][j] = 0.f;

    #pragma unroll
    for (int kk = 0; kk < 16; kk++) {
        unsigned a0, a1, a2, a3, b0, b1, b2, b3;
        ldsm4(a0, a1, a2, a3, aBase + kk*32);
        ldsm4(b0, b1, b2, b3, bBase + kk*32);
        mma_tf32(acc[0], a0, a1, a2, a3, b0, b1);
        mma_tf32(acc[1], a0, a1, a2, a3, b2, b3);
    }

    float* Pp = d_P + (size_t)bi*4096 + hq*32;
    #pragma unroll
    for (int u = 0; u < 2; u++)
        #pragma unroll
        for (int half = 0; half < 2; half++)
            #pragma unroll
            for (int cc = 0; cc < 2; cc++)
                Pp[(n0 + u*8 + 2*qc + cc)*128 + m0 + qr + half*8] =
                    acc[u][half*2 + cc];
}

// ---------------- fwd stage B: X = (1/128) E @ P, complex combine --------
// per warp: bi; C2[kc(32), n(32)] = sum_h Eout[kc,h] * P[h,n]
#define FB_SMEM (32*132*4 + 4*32*132*4)
__global__ __launch_bounds__(128) void k_fwdB() {
    extern __shared__ float sm[];
    float* Es = sm;                    // [32][132]
    float* Pt = sm + 32*132;           // [4 warps][32 n][132 h]
    int t = threadIdx.x, lane = t & 31, warp = t >> 5;
    int bi = blockIdx.x*4 + warp;

    for (int idx = t; idx < 4096; idx += 128)
        Es[(idx >> 7)*132 + (idx & 127)] = d_Eout[idx];
    float* Pw = Pt + warp*32*132;
    const float4* Pg = (const float4*)(d_P + (size_t)bi*4096);
    for (int r = 0; r < 32; r++) {
        float4 v = Pg[r*32 + lane];
        int base = r*132 + lane*4;
        Pw[base+0] = tf32f(v.x); Pw[base+1] = tf32f(v.y);
        Pw[base+2] = tf32f(v.z); Pw[base+3] = tf32f(v.w);
    }
    __syncthreads();

    int qr = lane >> 2, qc = lane & 3, lr = lane & 7, lg = lane >> 3;
    unsigned aBase = s2u(Es) + ((lr + (lg & 1)*8)*132 + (lg >> 1)*4)*4;
    unsigned bBase = s2u(Pw) + ((lr + (lg >> 1)*8)*132 + (lg & 1)*4)*4;

    float acc[2][4][4];
    #pragma unroll
    for (int m = 0; m < 2; m++)
        #pragma unroll
        for (int n = 0; n < 4; n++)
            #pragma unroll
            for (int j = 0; j < 4; j++) acc[m][n][j] = 0.f;

    #pragma unroll
    for (int kk = 0; kk < 16; kk++) {
        unsigned a[2][4];
        ldsm4(a[0][0], a[0][1], a[0][2], a[0][3], aBase + kk*32);
        ldsm4(a[1][0], a[1][1], a[1][2], a[1][3], aBase + 16*132*4 + kk*32);
        #pragma unroll
        for (int nb = 0; nb < 2; nb++) {
            unsigned b0, b1, b2, b3;
            ldsm4(b0, b1, b2, b3, bBase + nb*16*132*4 + kk*32);
            #pragma unroll
            for (int m = 0; m < 2; m++) {
                mma_tf32(acc[m][nb*2],   a[m][0], a[m][1], a[m][2], a[m][3], b0, b1);
                mma_tf32(acc[m][nb*2+1], a[m][0], a[m][1], a[m][2], a[m][3], b2, b3);
            }
        }
    }

    int b = bi >> 6, ci = bi & 63;
    #pragma unroll
    for (int nt = 0; nt < 2; nt++)
        #pragma unroll
        for (int half = 0; half < 2; half++)
            #pragma unroll
            for (int cc = 0; cc < 2; cc++) {
                int k = qr + half*8, l = nt*8 + 2*qc + cc;
                int j = half*2 + cc;
                float xr = (acc[0][nt][j]   - acc[1][nt+2][j]) * (1.f/128.f);
                float xi = (acc[0][nt+2][j] + acc[1][nt][j])   * (1.f/128.f);
                d_X[((size_t)b*256 + k*16 + l)*64 + ci] = make_float2(xr, xi);
            }
}

// ---------------- per-mode channel mixing (o-split x4) -------------------
__global__ __launch_bounds__(256) void k_mix() {
    __shared__ float2 Ws[64*16];    // [i][ol]
    __shared__ float2 Xs[16*64];    // [b][i]
    int kl = blockIdx.x, oq = blockIdx.y, t = threadIdx.x;
    for (int idx = t; idx < 1024; idx += 256)
        Ws[idx] = d_Wt[kl*4096 + (idx >> 4)*64 + oq*16 + (idx & 15)];
    for (int idx = t; idx < 1024; idx += 256)
        Xs[idx] = d_X[((size_t)(idx >> 6)*256 + kl)*64 + (idx & 63)];
    __syncthreads();
    int ol = t & 15, b = t >> 4;
    float yr = 0.f, yi = 0.f;
    #pragma unroll 8
    for (int i = 0; i < 64; i++) {
        float2 xv = Xs[b*64 + i];
        float2 wv = Ws[i*16 + ol];
        yr += xv.x*wv.x - xv.y*wv.y;
        yi += xv.x*wv.y + xv.y*wv.x;
    }
    d_Y[((size_t)b*256 + kl)*64 + oq*16 + ol] = make_float2(yr, yi);
}

// ---------------- inverse stage 1 (over k) -------------------------------
__global__ __launch_bounds__(256) void k_invh() {
    __shared__ float2 Ys[256];
    __shared__ float2 twd[128];
    int t = threadIdx.x, bo = blockIdx.x;
    int b = bo >> 6, o = bo & 63;
    if (t < 128) twd[t] = d_twdp[t];
    Ys[t] = d_Y[((size_t)b*256 + t)*64 + o];
    __syncthreads();
    #pragma unroll
    for (int rep = 0; rep < 8; rep++) {
        int idx = rep*256 + t;
        int h = idx >> 4, l = idx & 15;
        float zr = 0.f, zi = 0.f;
        #pragma unroll
        for (int k = 0; k < 16; k++) {
            float2 y = Ys[k*16 + l];
            float2 e = twd[(k*h) & 127];
            zr += y.x*e.x - y.y*e.y;
            zi += y.x*e.y + y.y*e.x;
        }
        float f = (l == 0 ? 1.f : 2.f) * (1.f/128.f);
        d_Z1[(((size_t)b*128 + h)*64 + o)*16 + l] =
            make_float2(tf32f(zr*f), tf32f(zi*f));
    }
}

// ---------------- fused final: C[64o,128w] = A[64,96] @ B[96,128] --------
#define KP 132   // Bt pitch ([n][k] layout); 4w mod 32 row banks, 16B aligned
#define AP 100
#define OUT_SMEM (128*KP*4 + 64*AP*4 + 128*4)
__global__ __launch_bounds__(256) void k_out(const float* __restrict__ x,
                                             const float* __restrict__ bw,
                                             const float* __restrict__ bb,
                                             float* __restrict__ out) {
    extern __shared__ float sm[];
    float* Bt  = sm;               // [128 w][KP]
    float* As  = Bt + 128*KP;      // [64 o][AP]
    float* bbp = As + 64*AP;

    int t = threadIdx.x;           // 256 = 8 warps
    int b = blockIdx.x >> 7, h = blockIdx.x & 127;

    // Bt cols 0..63: x[b,i,h,:] transposed (per-float, 4-way conflict max)
    for (int idx = t; idx < 8192; idx += 256) {
        int i = idx >> 7, w = idx & 127;
        float v = x[(((size_t)(b*64 + i))*128 + h)*128 + w];
        Bt[w*KP + i] = tf32f(v);
    }
    // Bt cols 64..95: twiddles (precomputed tf32)
    for (int idx = t; idx < 4096; idx += 256) {
        int lc = idx >> 7, w = idx & 127;
        Bt[w*KP + 64 + lc] = d_Eout[idx];
    }
    // As cols 0..63: bw[o][i];  cols 64..95: Zr|Zi
    for (int idx = t; idx < 4096; idx += 256)
        As[(idx >> 6)*AP + (idx & 63)] = tf32f(bw[idx]);
    for (int idx = t; idx < 1024; idx += 256) {
        int o = idx >> 4, l = idx & 15;
        float2 z = d_Z1[(((size_t)b*128 + h)*64 + o)*16 + l];
        As[o*AP + 64 + l] = z.x;
        As[o*AP + 80 + l] = z.y;
    }
    if (t < 64) bbp[t] = bb[t];
    else if (t < 128) bbp[t] = d_proj[b*64 + (t - 64)];
    __syncthreads();

    int lane = t & 31, warp = t >> 5;
    int m0 = (warp & 3) * 16, n0 = (warp >> 2) * 64;
    int qr = lane >> 2, qc = lane & 3;
    int lr = lane & 7, lg = lane >> 3;

    unsigned aBase = s2u(As) + ((m0 + lr + (lg & 1)*8)*AP + (lg >> 1)*4)*4;
    unsigned bBase = s2u(Bt) + ((n0 + lr + (lg >> 1)*8)*KP + (lg & 1)*4)*4;

    float acc[8][4];
    #pragma unroll
    for (int nt = 0; nt < 8; nt++)
        #pragma unroll
        for (int j = 0; j < 4; j++) acc[nt][j] = 0.f;

    #pragma unroll
    for (int kk = 0; kk < 12; kk++) {
        unsigned a0, a1, a2, a3;
        ldsm4(a0, a1, a2, a3, aBase + kk*32);
        #pragma unroll
        for (int p = 0; p < 4; p++) {
            unsigned b0, b1, b2, b3;
            ldsm4(b0, b1, b2, b3, bBase + p*16*KP*4 + kk*32);
            mma_tf32(acc[2*p],   a0, a1, a2, a3, b0, b1);
            mma_tf32(acc[2*p+1], a0, a1, a2, a3, b2, b3);
        }
    }

    #pragma unroll
    for (int nt = 0; nt < 8; nt++) {
        #pragma unroll
        for (int half = 0; half < 2; half++) {
            int o = m0 + qr + half*8;
            float bias = bbp[o], pr = bbp[64 + o];
            float v0 = acc[nt][half*2 + 0] + bias;
            float v1 = acc[nt][half*2 + 1] + bias;
            v0 = 0.5f * v0 * (1.f + erff(v0 * 0.70710678118f)) + pr;
            v1 = 0.5f * v1 * (1.f + erff(v1 * 0.70710678118f)) + pr;
            int w = n0 + nt*8 + qc*2;
            *(float2*)(out + (((size_t)(b*64 + o))*128 + h)*128 + w) =
                make_float2(v0, v1);
        }
    }
}

// ---------------- launcher ----------------------------------------------
extern "C" void kernel_launch(void* const* d_in, const int* in_sizes, int n_in,
                              void* d_out, int out_size) {
    const float* x    = (const float*)d_in[0];
    const float* temb = (const float*)d_in[1];
    const float* wr   = (const float*)d_in[2];
    const float* wi   = (const float*)d_in[3];
    const float* bw   = (const float*)d_in[4];
    const float* bb   = (const float*)d_in[5];
    const float* twm  = (const float*)d_in[6];
    const float* tbv  = (const float*)d_in[7];
    float* out = (float*)d_out;

    cudaFuncSetAttribute(k_fwdB, cudaFuncAttributeMaxDynamicSharedMemorySize, FB_SMEM);
    cudaFuncSetAttribute(k_out,  cudaFuncAttributeMaxDynamicSharedMemorySize, OUT_SMEM);

    k_prep<<<1, 256>>>();
    k_proj<<<dim3(NB, 8), 256>>>(temb, twm, tbv);
    k_wt  <<<dim3(8, 128), dim3(32, 8)>>>(wr, wi);
    k_fwdA<<<dim3(1024, 4), 128>>>(x);
    k_fwdB<<<256, 128, FB_SMEM>>>();
    k_mix <<<dim3(256, 4), 256>>>();
    k_invh<<<NB*NC, 256>>>();
    k_out <<<NB*NH, 256, OUT_SMEM>>>(x, bw, bb, out);
}

// round 9
// speedup vs baseline: 2.4755x; 1.5786x over previous
#include <cuda_runtime.h>
#include <math.h>

#define NB 16
#define NC 64
#define NH 128
#define NW 128
#define PI2 6.283185307179586f

// ---------------- scratch ------------------------------------------------
__device__ float  d_P [1024*4096];        // [bi][n(0..31: Pr|Pi)][h]  (tf32-rounded)
__device__ float2 d_X [NB*256*64];        // [b][kl][i]
__device__ float2 d_Y [NB*256*64];        // [b][kl][o]
__device__ float  d_Z1[NB*NH*64*32];      // [b][h][o][0..15 zr |16..31 zi] (tf32)
__device__ float2 d_Wt[256*64*64];        // [kl][i*64+o]
__device__ float  d_proj[NB*NC];
__device__ float  d_Eout [32*128];        // [n][w]: n<16 cos, n>=16 -sin (tf32)
__device__ float  d_EoutT[128*32];        // [w][n]  transposed copy
__device__ float2 d_twdp[128];            // e^{+i 2pi m/128}

// ---------------- helpers ------------------------------------------------
__device__ __forceinline__ unsigned tf32u(float f) {
    unsigned r; asm("cvt.rna.tf32.f32 %0, %1;" : "=r"(r) : "f"(f)); return r;
}
__device__ __forceinline__ float tf32f(float f) { return __uint_as_float(tf32u(f)); }
__device__ __forceinline__ void mma_tf32(float* c,
    unsigned a0, unsigned a1, unsigned a2, unsigned a3, unsigned b0, unsigned b1) {
    asm volatile(
        "mma.sync.aligned.m16n8k8.row.col.f32.tf32.tf32.f32 "
        "{%0,%1,%2,%3}, {%4,%5,%6,%7}, {%8,%9}, {%0,%1,%2,%3};"
        : "+f"(c[0]), "+f"(c[1]), "+f"(c[2]), "+f"(c[3])
        : "r"(a0), "r"(a1), "r"(a2), "r"(a3), "r"(b0), "r"(b1));
}
__device__ __forceinline__ unsigned s2u(const void* p) {
    unsigned a;
    asm("{ .reg .u64 t; cvta.to.shared.u64 t, %1; cvt.u32.u64 %0, t; }" : "=r"(a) : "l"(p));
    return a;
}
__device__ __forceinline__ void ldsm4(unsigned &r0, unsigned &r1, unsigned &r2,
                                      unsigned &r3, unsigned a) {
    asm volatile("ldmatrix.sync.aligned.m8n8.x4.shared.b16 {%0,%1,%2,%3}, [%4];"
        : "=r"(r0), "=r"(r1), "=r"(r2), "=r"(r3) : "r"(a));
}
__device__ __forceinline__ void cpa16(unsigned dst, const void* src) {
    asm volatile("cp.async.ca.shared.global [%0], [%1], 16;" :: "r"(dst), "l"(src));
}
__device__ __forceinline__ void cpa_wait() {
    asm volatile("cp.async.commit_group;");
    asm volatile("cp.async.wait_group 0;" ::: "memory");
}

// ---------------- precompute ---------------------------------------------
__global__ void k_prep() {
    int t = threadIdx.x;                       // 256
    for (int idx = t; idx < 4096; idx += 256) {
        int r = idx >> 7, w = idx & 127;
        int l = r & 15;
        float s, c;
        sincosf(PI2 * (float)((l*w) & 127) * (1.f/128.f), &s, &c);
        float v = tf32f(r < 16 ? c : -s);
        d_Eout[idx] = v;
        d_EoutT[w*32 + r] = v;
    }
    if (t < 128) {
        float s, c; sincosf(PI2 * t * (1.f/128.f), &s, &c);
        d_twdp[t] = make_float2(c, s);
    }
}

// ---------------- temb projection ---------------------------------------
__global__ void k_proj(const float* __restrict__ temb,
                       const float* __restrict__ twm,
                       const float* __restrict__ tbv) {
    __shared__ float s_silu[512];
    int b = blockIdx.x, cg = blockIdx.y, t = threadIdx.x;   // 256 threads
    for (int j = t; j < 512; j += 256) {
        float v = temb[b*512 + j];
        s_silu[j] = v / (1.f + __expf(-v));
    }
    __syncthreads();
    int w = t >> 5, lane = t & 31;
    int c = cg*8 + w;
    float acc = 0.f;
    #pragma unroll 4
    for (int j = lane; j < 512; j += 32) acc += s_silu[j] * twm[c*512 + j];
    #pragma unroll
    for (int off = 16; off > 0; off >>= 1)
        acc += __shfl_xor_sync(0xffffffffu, acc, off);
    if (lane == 0) d_proj[b*64 + c] = acc + tbv[c];
}

// ---------------- weight transpose: [i,o,k,l] -> [kl][i*64+o] ------------
__global__ void k_wt(const float* __restrict__ wr, const float* __restrict__ wi) {
    __shared__ float tr[32][33], ti[32][33];
    int kl0 = blockIdx.x * 32, io0 = blockIdx.y * 32;
    for (int r = threadIdx.y; r < 32; r += 8) {
        tr[r][threadIdx.x] = wr[(io0 + r)*256 + kl0 + threadIdx.x];
        ti[r][threadIdx.x] = wi[(io0 + r)*256 + kl0 + threadIdx.x];
    }
    __syncthreads();
    for (int r = threadIdx.y; r < 32; r += 8) {
        d_Wt[(kl0 + r)*4096 + io0 + threadIdx.x] =
            make_float2(tr[threadIdx.x][r], ti[threadIdx.x][r]);
    }
}

// ---------------- fwd stage A: P[bi][n][h] = x(h-tile) @ E^T --------------
// 2 bi per block; grid (512 bip, 4 hq), 256 thr
#define FA_SMEM ((2*32*132 + 32*132)*4)
__global__ __launch_bounds__(256) void k_fwdA(const float* __restrict__ x) {
    extern __shared__ float sm[];
    float* xs = sm;                    // [2 bl][32 h][132]
    float* Es = sm + 2*32*132;         // [32 n][132]
    int t = threadIdx.x;
    int bi0 = blockIdx.x*2, hq = blockIdx.y;

    unsigned xsA = s2u(xs), EsA = s2u(Es);
    for (int idx = t; idx < 2048; idx += 256) {
        int bl = idx >> 10, rem = idx & 1023;
        int hh = rem >> 5, w4 = rem & 31;
        cpa16(xsA + (bl*4224 + hh*132 + w4*4)*4,
              x + (size_t)(bi0 + bl)*16384 + hq*4096 + hh*128 + w4*4);
    }
    for (int idx = t; idx < 1024; idx += 256) {
        int r = idx >> 5, c4 = idx & 31;
        cpa16(EsA + (r*132 + c4*4)*4, d_Eout + r*128 + c4*4);
    }
    cpa_wait();
    __syncthreads();

    int lane = t & 31, warp = t >> 5;
    int bl = warp >> 2, wq = warp & 3;
    int m0 = (wq & 1)*16, n0 = (wq >> 1)*16;
    int qr = lane >> 2, qc = lane & 3, lr = lane & 7, lg = lane >> 3;

    unsigned aBase = xsA + bl*4224*4 + ((m0 + lr + (lg & 1)*8)*132 + (lg >> 1)*4)*4;
    unsigned bBase = EsA + ((n0 + lr + (lg >> 1)*8)*132 + (lg & 1)*4)*4;

    float acc[2][4];
    #pragma unroll
    for (int g = 0; g < 2; g++)
        #pragma unroll
        for (int j = 0; j < 4; j++) acc[g][j] = 0.f;

    #pragma unroll
    for (int kk = 0; kk < 16; kk++) {
        unsigned a0, a1, a2, a3, b0, b1, b2, b3;
        ldsm4(a0, a1, a2, a3, aBase + kk*32);
        ldsm4(b0, b1, b2, b3, bBase + kk*32);
        mma_tf32(acc[0], a0, a1, a2, a3, b0, b1);
        mma_tf32(acc[1], a0, a1, a2, a3, b2, b3);
    }

    float* Pp = d_P + (size_t)(bi0 + bl)*4096 + hq*32;
    #pragma unroll
    for (int g = 0; g < 2; g++)
        #pragma unroll
        for (int half = 0; half < 2; half++)
            #pragma unroll
            for (int cc = 0; cc < 2; cc++)
                Pp[(n0 + g*8 + 2*qc + cc)*128 + m0 + qr + half*8] =
                    tf32f(acc[g][half*2 + cc]);
}

// ---------------- fwd stage B: X = (1/128) E @ P, complex combine --------
#define FB_SMEM (32*132*4 + 4*32*132*4)
__global__ __launch_bounds__(128) void k_fwdB() {
    extern __shared__ float sm[];
    float* Es = sm;                    // [32][132]
    float* Pt = sm + 32*132;           // [4 warps][32 n][132 h]
    int t = threadIdx.x, lane = t & 31, warp = t >> 5;
    int bi = blockIdx.x*4 + warp;

    unsigned EsA = s2u(Es);
    for (int idx = t; idx < 1024; idx += 128) {
        int r = idx >> 5, c4 = idx & 31;
        cpa16(EsA + (r*132 + c4*4)*4, d_Eout + r*128 + c4*4);
    }
    float* Pw = Pt + warp*32*132;
    unsigned PwA = s2u(Pw);
    const float* Pg = d_P + (size_t)bi*4096;
    #pragma unroll 8
    for (int r = 0; r < 32; r++)
        cpa16(PwA + (r*132 + lane*4)*4, Pg + r*128 + lane*4);
    cpa_wait();
    __syncthreads();

    int qr = lane >> 2, qc = lane & 3, lr = lane & 7, lg = lane >> 3;
    unsigned aBase = EsA + ((lr + (lg & 1)*8)*132 + (lg >> 1)*4)*4;
    unsigned bBase = PwA + ((lr + (lg >> 1)*8)*132 + (lg & 1)*4)*4;

    float acc[2][4][4];
    #pragma unroll
    for (int m = 0; m < 2; m++)
        #pragma unroll
        for (int n = 0; n < 4; n++)
            #pragma unroll
            for (int j = 0; j < 4; j++) acc[m][n][j] = 0.f;

    #pragma unroll
    for (int kk = 0; kk < 16; kk++) {
        unsigned a[2][4];
        ldsm4(a[0][0], a[0][1], a[0][2], a[0][3], aBase + kk*32);
        ldsm4(a[1][0], a[1][1], a[1][2], a[1][3], aBase + 16*132*4 + kk*32);
        #pragma unroll
        for (int nb = 0; nb < 2; nb++) {
            unsigned b0, b1, b2, b3;
            ldsm4(b0, b1, b2, b3, bBase + nb*16*132*4 + kk*32);
            #pragma unroll
            for (int m = 0; m < 2; m++) {
                mma_tf32(acc[m][nb*2],   a[m][0], a[m][1], a[m][2], a[m][3], b0, b1);
                mma_tf32(acc[m][nb*2+1], a[m][0], a[m][1], a[m][2], a[m][3], b2, b3);
            }
        }
    }

    int b = bi >> 6, ci = bi & 63;
    #pragma unroll
    for (int nt = 0; nt < 2; nt++)
        #pragma unroll
        for (int half = 0; half < 2; half++)
            #pragma unroll
            for (int cc = 0; cc < 2; cc++) {
                int k = qr + half*8, l = nt*8 + 2*qc + cc;
                int j = half*2 + cc;
                float xr = (acc[0][nt][j]   - acc[1][nt+2][j]) * (1.f/128.f);
                float xi = (acc[0][nt+2][j] + acc[1][nt][j])   * (1.f/128.f);
                d_X[((size_t)b*256 + k*16 + l)*64 + ci] = make_float2(xr, xi);
            }
}

// ---------------- per-mode channel mixing (o-split x4) -------------------
__global__ __launch_bounds__(256) void k_mix() {
    __shared__ float2 Ws[64*16];    // [i][ol]
    __shared__ float2 Xs[16*64];    // [b][i]
    int kl = blockIdx.x, oq = blockIdx.y, t = threadIdx.x;
    for (int idx = t; idx < 1024; idx += 256)
        Ws[idx] = d_Wt[kl*4096 + (idx >> 4)*64 + oq*16 + (idx & 15)];
    for (int idx = t; idx < 1024; idx += 256)
        Xs[idx] = d_X[((size_t)(idx >> 6)*256 + kl)*64 + (idx & 63)];
    __syncthreads();
    int ol = t & 15, b = t >> 4;
    float yr = 0.f, yi = 0.f;
    #pragma unroll 8
    for (int i = 0; i < 64; i++) {
        float2 xv = Xs[b*64 + i];
        float2 wv = Ws[i*16 + ol];
        yr += xv.x*wv.x - xv.y*wv.y;
        yi += xv.x*wv.y + xv.y*wv.x;
    }
    d_Y[((size_t)b*256 + kl)*64 + oq*16 + ol] = make_float2(yr, yi);
}

// ---------------- inverse stage 1 (over k) -------------------------------
__global__ __launch_bounds__(256) void k_invh() {
    __shared__ float2 Ys[256];
    __shared__ float2 twd[128];
    int t = threadIdx.x, bo = blockIdx.x;
    int b = bo >> 6, o = bo & 63;
    if (t < 128) twd[t] = d_twdp[t];
    Ys[t] = d_Y[((size_t)b*256 + t)*64 + o];
    __syncthreads();
    #pragma unroll
    for (int rep = 0; rep < 8; rep++) {
        int idx = rep*256 + t;
        int h = idx >> 4, l = idx & 15;
        float zr = 0.f, zi = 0.f;
        #pragma unroll
        for (int k = 0; k < 16; k++) {
            float2 y = Ys[k*16 + l];
            float2 e = twd[(k*h) & 127];
            zr += y.x*e.x - y.y*e.y;
            zi += y.x*e.y + y.y*e.x;
        }
        float f = (l == 0 ? 1.f : 2.f) * (1.f/128.f);
        float* zp = d_Z1 + (((size_t)b*128 + h)*64 + o)*32;
        zp[l]      = tf32f(zr*f);
        zp[16 + l] = tf32f(zi*f);
    }
}

// ---------------- fused final (w-split): C[64o,64w] = A[64,96]@B[96,64] --
#define KP 100
#define AP 100
#define OUT_SMEM ((64*KP + 64*AP + 128)*4)
__global__ __launch_bounds__(256) void k_out(const float* __restrict__ x,
                                             const float* __restrict__ bw,
                                             const float* __restrict__ bb,
                                             float* __restrict__ out) {
    extern __shared__ float sm[];
    float* Bt  = sm;               // [64 w][KP]
    float* As  = Bt + 64*KP;       // [64 o][AP]
    float* bbp = As + 64*AP;

    int t = threadIdx.x;           // 256 = 8 warps
    int b = blockIdx.x >> 7, h = blockIdx.x & 127;
    int wq = blockIdx.y;           // 0/1 -> w half

    unsigned BtA = s2u(Bt), AsA = s2u(As);

    // As cols 0..63: bw rows (raw f32, HW-truncated by mma)
    for (int idx = t; idx < 1024; idx += 256) {
        int o = idx >> 4, c4 = idx & 15;
        cpa16(AsA + (o*AP + c4*4)*4, bw + o*64 + c4*4);
    }
    // As cols 64..95: Z1 row (zr|zi, pre-rounded)
    for (int idx = t; idx < 512; idx += 256) {
        int o = idx >> 3, c4 = idx & 7;
        cpa16(AsA + (o*AP + 64 + c4*4)*4,
              d_Z1 + (((size_t)b*128 + h)*64 + o)*32 + c4*4);
    }
    // Bt cols 64..95: EoutT rows
    for (int idx = t; idx < 512; idx += 256) {
        int w = idx >> 3, c4 = idx & 7;
        cpa16(BtA + (w*KP + 64 + c4*4)*4, d_EoutT + (wq*64 + w)*32 + c4*4);
    }
    // Bt cols 0..63: x transposed (raw f32)
    for (int idx = t; idx < 1024; idx += 256) {
        int i = idx >> 4, w4 = idx & 15;
        float4 v = *(const float4*)(x + (((size_t)(b*64 + i))*128 + h)*128
                                      + wq*64 + w4*4);
        Bt[(w4*4+0)*KP + i] = v.x;
        Bt[(w4*4+1)*KP + i] = v.y;
        Bt[(w4*4+2)*KP + i] = v.z;
        Bt[(w4*4+3)*KP + i] = v.w;
    }
    if (t < 64) bbp[t] = bb[t];
    else if (t < 128) bbp[t] = d_proj[b*64 + (t - 64)];
    cpa_wait();
    __syncthreads();

    int lane = t & 31, warp = t >> 5;
    int m0 = (warp & 3) * 16, n0 = (warp >> 2) * 32;
    int qr = lane >> 2, qc = lane & 3;
    int lr = lane & 7, lg = lane >> 3;

    unsigned aBase = AsA + ((m0 + lr + (lg & 1)*8)*AP + (lg >> 1)*4)*4;
    unsigned bBase = BtA + ((n0 + lr + (lg >> 1)*8)*KP + (lg & 1)*4)*4;

    float acc[4][4];
    #pragma unroll
    for (int nt = 0; nt < 4; nt++)
        #pragma unroll
        for (int j = 0; j < 4; j++) acc[nt][j] = 0.f;

    #pragma unroll
    for (int kk = 0; kk < 12; kk++) {
        unsigned a0, a1, a2, a3;
        ldsm4(a0, a1, a2, a3, aBase + kk*32);
        #pragma unroll
        for (int p = 0; p < 2; p++) {
            unsigned b0, b1, b2, b3;
            ldsm4(b0, b1, b2, b3, bBase + p*16*KP*4 + kk*32);
            mma_tf32(acc[2*p],   a0, a1, a2, a3, b0, b1);
            mma_tf32(acc[2*p+1], a0, a1, a2, a3, b2, b3);
        }
    }

    #pragma unroll
    for (int nt = 0; nt < 4; nt++) {
        #pragma unroll
        for (int half = 0; half < 2; half++) {
            int o = m0 + qr + half*8;
            float bias = bbp[o], pr = bbp[64 + o];
            float v0 = acc[nt][half*2 + 0] + bias;
            float v1 = acc[nt][half*2 + 1] + bias;
            v0 = 0.5f * v0 * (1.f + erff(v0 * 0.70710678118f)) + pr;
            v1 = 0.5f * v1 * (1.f + erff(v1 * 0.70710678118f)) + pr;
            int w = wq*64 + n0 + nt*8 + qc*2;
            *(float2*)(out + (((size_t)(b*64 + o))*128 + h)*128 + w) =
                make_float2(v0, v1);
        }
    }
}

// ---------------- launcher ----------------------------------------------
extern "C" void kernel_launch(void* const* d_in, const int* in_sizes, int n_in,
                              void* d_out, int out_size) {
    const float* x    = (const float*)d_in[0];
    const float* temb = (const float*)d_in[1];
    const float* wr   = (const float*)d_in[2];
    const float* wi   = (const float*)d_in[3];
    const float* bw   = (const float*)d_in[4];
    const float* bb   = (const float*)d_in[5];
    const float* twm  = (const float*)d_in[6];
    const float* tbv  = (const float*)d_in[7];
    float* out = (float*)d_out;

    cudaFuncSetAttribute(k_fwdA, cudaFuncAttributeMaxDynamicSharedMemorySize, FA_SMEM);
    cudaFuncSetAttribute(k_fwdB, cudaFuncAttributeMaxDynamicSharedMemorySize, FB_SMEM);
    cudaFuncSetAttribute(k_out,  cudaFuncAttributeMaxDynamicSharedMemorySize, OUT_SMEM);

    k_prep<<<1, 256>>>();
    k_proj<<<dim3(NB, 8), 256>>>(temb, twm, tbv);
    k_wt  <<<dim3(8, 128), dim3(32, 8)>>>(wr, wi);
    k_fwdA<<<dim3(512, 4), 256, FA_SMEM>>>(x);
    k_fwdB<<<256, 128, FB_SMEM>>>();
    k_mix <<<dim3(256, 4), 256>>>();
    k_invh<<<NB*NC, 256>>>();
    k_out <<<dim3(NB*NH, 2), 256, OUT_SMEM>>>(x, bw, bb, out);
}